// round 7
// baseline (speedup 1.0000x reference)
#include <cuda_runtime.h>
#include <math.h>

#define BB      32
#define HH      32
#define KVHN    8
#define DD      128
#define SS      2048
#define NCHUNK  32
#define CS      64            // positions per chunk
#define NT      256           // 8 warps = 8 kv heads
#define SCALE   0.08838834764831845f
#define ROWF    (KVHN*DD)     // floats per slot row (1024)
#define FULLM   0xffffffffu

typedef unsigned long long ull;

__device__ float g_acc[(size_t)BB * NCHUNK * HH * DD];  // 16 MB
__device__ float g_m[BB * NCHUNK * HH];
__device__ float g_l[BB * NCHUNK * HH];

union F4U2 { float4 f; float s[4]; ull u[2]; };

__device__ __forceinline__ ull ffma2(ull a, ull b, ull c) {
    ull d; asm("fma.rn.f32x2 %0, %1, %2, %3;" : "=l"(d) : "l"(a), "l"(b), "l"(c));
    return d;
}
__device__ __forceinline__ ull fmul2(ull a, ull b) {
    ull d; asm("mul.rn.f32x2 %0, %1, %2;" : "=l"(d) : "l"(a), "l"(b));
    return d;
}
__device__ __forceinline__ ull fdup(float x) {
    ull d; unsigned xi = __float_as_uint(x);
    asm("mov.b64 %0, {%1, %1};" : "=l"(d) : "r"(xi));
    return d;
}
__device__ __forceinline__ float hadd2(ull a) {
    float2 f; asm("mov.b64 {%0, %1}, %2;" : "=f"(f.x), "=f"(f.y) : "l"(a));
    return f.x + f.y;
}

// fp32 Cody-Waite reduction into [-pi,pi] then accurate sincos
__device__ __forceinline__ void rope_sincos(float ang, float* s, float* c) {
    const float INV2PI = 0.15915494309189535f;
    const float C1 = 6.28125f;
    const float C2 = 0.0019353071795864769f;
    float n = rintf(ang * INV2PI);
    float r = fmaf(-n, C1, ang);
    r = fmaf(-n, C2, r);
    sincosf(r, s, c);
}

__global__ __launch_bounds__(NT, 3) void attn_partial(
    const float* __restrict__ q,
    const float* __restrict__ kc,
    const float* __restrict__ vc,
    const int*   __restrict__ slot_map,
    const int*   __restrict__ pos)
{
    __shared__ float  cos_tab[CS * 64];    // 16 KB
    __shared__ float  sin_tab[CS * 64];    // 16 KB
    __shared__ float4 sc_sm[KVHN * CS];    // 8 KB   scores -> exp weights
    __shared__ int    slot_sm[CS];
    __shared__ float  invf_sm[64];

    const int b     = blockIdx.y;
    const int chunk = blockIdx.x;
    const int s0    = chunk * CS;
    const int tid   = threadIdx.x;
    const int w     = tid >> 5;            // warp = kv head
    const int l     = tid & 31;
    const int c     = l & 15;              // float4 chunk within row (K phase)
    const int r     = l >> 4;              // row parity within pair
    const int hsel  = c & 3;               // head this lane finalizes

    if (tid < 64) {
        float fi = (float)tid * 0.015625f;
        invf_sm[tid] = expf(-fi * 9.210340371976184f);
    }
    if (tid < CS) slot_sm[tid] = slot_map[b * SS + s0 + tid];
    __syncthreads();

    // cos/sin tables for all CS positions (shared by all 8 kv heads)
    for (int idx = tid; idx < CS * 64; idx += NT) {
        int s = idx >> 6;
        int i = idx & 63;
        float p = (float)pos[b * SS + s0 + s];
        float sv, cv;
        rope_sincos(p * invf_sm[i], &sv, &cv);
        cos_tab[idx] = cv;
        sin_tab[idx] = sv;
    }

    // Rope q (4 heads per warp) for this lane's dims {4c..4c+3, +64}; fold SCALE.
    // Packed f32x2 layout: qlo[j].u[0]=(d0,d1), u[1]=(d2,d3).
    F4U2 qlo[4], qhi[4];
    {
        float pq = (float)pos[b * SS + SS - 1];
        float cq[4], sq[4];
        #pragma unroll
        for (int i = 0; i < 4; i++)
            rope_sincos(pq * invf_sm[4 * c + i], &sq[i], &cq[i]);
        #pragma unroll
        for (int j = 0; j < 4; j++) {
            const float4* qp = (const float4*)(q + ((size_t)(b * HH + w * 4 + j)) * DD);
            float4 alo = qp[c];
            float4 ahi = qp[c + 16];
            qlo[j].f.x = SCALE * (alo.x * cq[0] - ahi.x * sq[0]);
            qhi[j].f.x = SCALE * (ahi.x * cq[0] + alo.x * sq[0]);
            qlo[j].f.y = SCALE * (alo.y * cq[1] - ahi.y * sq[1]);
            qhi[j].f.y = SCALE * (ahi.y * cq[1] + alo.y * sq[1]);
            qlo[j].f.z = SCALE * (alo.z * cq[2] - ahi.z * sq[2]);
            qhi[j].f.z = SCALE * (ahi.z * cq[2] + alo.z * sq[2]);
            qlo[j].f.w = SCALE * (alo.w * cq[3] - ahi.w * sq[3]);
            qhi[j].f.w = SCALE * (ahi.w * cq[3] + alo.w * sq[3]);
        }
    }
    __syncthreads();

    // ---- K phase: 2 rows per iteration (half-warp each), packed math ----
    float msel = -1e30f;   // running max for head hsel over rows this lane saw
    #pragma unroll 2
    for (int sp = 0; sp < CS; sp += 2) {
        const int s = sp + r;
        const int slot = slot_sm[s];
        F4U2 klo, khi;
        klo.f = make_float4(0.f, 0.f, 0.f, 0.f);
        khi.f = make_float4(0.f, 0.f, 0.f, 0.f);
        if (slot >= 0) {
            const float* kp = kc + (size_t)slot * ROWF + w * DD + 4 * c;
            klo.f = *(const float4*)kp;
            khi.f = *(const float4*)(kp + 64);
        }
        F4U2 co, si;
        co.f = *(const float4*)&cos_tab[s * 64 + 4 * c];
        si.f = *(const float4*)&sin_tab[s * 64 + 4 * c];

        ull p0 = 0, p1 = 0, p2 = 0, p3 = 0;   // (0.f,0.f) bit pattern
        #pragma unroll
        for (int h2 = 0; h2 < 2; h2++) {
            ull nsi = si.u[h2] ^ 0x8000000080000000ULL;
            ull rl = ffma2(khi.u[h2], nsi,      fmul2(klo.u[h2], co.u[h2]));
            ull rh = ffma2(klo.u[h2], si.u[h2], fmul2(khi.u[h2], co.u[h2]));
            p0 = ffma2(qlo[0].u[h2], rl, p0);  p0 = ffma2(qhi[0].u[h2], rh, p0);
            p1 = ffma2(qlo[1].u[h2], rl, p1);  p1 = ffma2(qhi[1].u[h2], rh, p1);
            p2 = ffma2(qlo[2].u[h2], rl, p2);  p2 = ffma2(qhi[2].u[h2], rh, p2);
            p3 = ffma2(qlo[3].u[h2], rl, p3);  p3 = ffma2(qhi[3].u[h2], rh, p3);
        }
        float v0 = hadd2(p0), v1 = hadd2(p1), v2 = hadd2(p2), v3 = hadd2(p3);

        // reduce all 4 heads within each aligned 4-lane group (off 1,2)
        v0 += __shfl_xor_sync(FULLM, v0, 1);
        v1 += __shfl_xor_sync(FULLM, v1, 1);
        v2 += __shfl_xor_sync(FULLM, v2, 1);
        v3 += __shfl_xor_sync(FULLM, v3, 1);
        v0 += __shfl_xor_sync(FULLM, v0, 2);
        v1 += __shfl_xor_sync(FULLM, v1, 2);
        v2 += __shfl_xor_sync(FULLM, v2, 2);
        v3 += __shfl_xor_sync(FULLM, v3, 2);
        // lane picks its head, finishes over the 4 groups (off 4,8)
        float sv = (hsel == 0) ? v0 : (hsel == 1) ? v1 : (hsel == 2) ? v2 : v3;
        sv += __shfl_xor_sync(FULLM, sv, 4);
        sv += __shfl_xor_sync(FULLM, sv, 8);
        msel = fmaxf(msel, sv);
        if (c < 4) ((float*)&sc_sm[w * CS + s])[c] = sv;
    }
    // merge row-parity halves; broadcast the 4 head maxima
    msel = fmaxf(msel, __shfl_xor_sync(FULLM, msel, 16));
    const float m0 = __shfl_sync(FULLM, msel, 0);
    const float m1 = __shfl_sync(FULLM, msel, 1);
    const float m2 = __shfl_sync(FULLM, msel, 2);
    const float m3 = __shfl_sync(FULLM, msel, 3);
    __syncwarp();

    // ---- scores -> exp weights in shared; also compute l-sums here ----
    float l0, l1, l2, l3;
    {
        float4 sca = sc_sm[w * CS + l];
        sca.x = __expf(sca.x - m0); sca.y = __expf(sca.y - m1);
        sca.z = __expf(sca.z - m2); sca.w = __expf(sca.w - m3);
        sc_sm[w * CS + l] = sca;
        float4 scb = sc_sm[w * CS + 32 + l];
        scb.x = __expf(scb.x - m0); scb.y = __expf(scb.y - m1);
        scb.z = __expf(scb.z - m2); scb.w = __expf(scb.w - m3);
        sc_sm[w * CS + 32 + l] = scb;
        l0 = sca.x + scb.x; l1 = sca.y + scb.y;
        l2 = sca.z + scb.z; l3 = sca.w + scb.w;
        #pragma unroll
        for (int off = 16; off > 0; off >>= 1) {
            l0 += __shfl_xor_sync(FULLM, l0, off);
            l1 += __shfl_xor_sync(FULLM, l1, off);
            l2 += __shfl_xor_sync(FULLM, l2, off);
            l3 += __shfl_xor_sync(FULLM, l3, off);
        }
    }
    __syncwarp();

    // ---- V phase: lane owns dims 4l..4l+3, packed accumulate ----
    ull a0l = 0, a0h = 0, a1l = 0, a1h = 0, a2l = 0, a2h = 0, a3l = 0, a3h = 0;
    #pragma unroll 4
    for (int s = 0; s < CS; s++) {
        const float4 e = sc_sm[w * CS + s];     // broadcast
        const int slot = slot_sm[s];
        F4U2 v4;
        v4.f = make_float4(0.f, 0.f, 0.f, 0.f);
        if (slot >= 0)
            v4.f = *(const float4*)(vc + (size_t)slot * ROWF + w * DD + 4 * l);
        ull e0 = fdup(e.x), e1 = fdup(e.y), e2 = fdup(e.z), e3 = fdup(e.w);
        a0l = ffma2(e0, v4.u[0], a0l); a0h = ffma2(e0, v4.u[1], a0h);
        a1l = ffma2(e1, v4.u[0], a1l); a1h = ffma2(e1, v4.u[1], a1h);
        a2l = ffma2(e2, v4.u[0], a2l); a2h = ffma2(e2, v4.u[1], a2h);
        a3l = ffma2(e3, v4.u[0], a3l); a3h = ffma2(e3, v4.u[1], a3h);
    }

    // ---- Write partials (float4, coalesced) ----
    {
        size_t base = (((size_t)b * NCHUNK + chunk) * HH + w * 4) * DD;
        float4* ga = (float4*)g_acc;
        F4U2 t;
        t.u[0] = a0l; t.u[1] = a0h; ga[(base >> 2) + l]            = t.f;
        t.u[0] = a1l; t.u[1] = a1h; ga[((base + DD) >> 2) + l]     = t.f;
        t.u[0] = a2l; t.u[1] = a2h; ga[((base + 2 * DD) >> 2) + l] = t.f;
        t.u[0] = a3l; t.u[1] = a3h; ga[((base + 3 * DD) >> 2) + l] = t.f;
    }
    if (l == 0) {
        int mb = (b * NCHUNK + chunk) * HH + w * 4;
        g_m[mb + 0] = m0; g_m[mb + 1] = m1; g_m[mb + 2] = m2; g_m[mb + 3] = m3;
        g_l[mb + 0] = l0; g_l[mb + 1] = l1; g_l[mb + 2] = l2; g_l[mb + 3] = l3;
    }
}

// Combine: one block per (b,h); 4 warps x 8 chunks each; merge via shared.
__global__ __launch_bounds__(128) void attn_combine(float* __restrict__ out)
{
    __shared__ float4 osm[4][32];
    __shared__ float  Lsm[4];

    const int bh = blockIdx.x;
    const int b  = bh >> 5;
    const int h  = bh & 31;
    const int wj = threadIdx.x >> 5;
    const int l  = threadIdx.x & 31;

    float mraw = g_m[(b * NCHUNK + l) * HH + h];
    float M = mraw;
    #pragma unroll
    for (int off = 16; off > 0; off >>= 1)
        M = fmaxf(M, __shfl_xor_sync(FULLM, M, off));

    // precompute all 8 alpha factors so the load loop has full MLP
    float al[8];
    #pragma unroll
    for (int k = 0; k < 8; k++)
        al[k] = __expf(__shfl_sync(FULLM, mraw, wj * 8 + k) - M);

    float L = 0.f;
    float4 o = make_float4(0.f, 0.f, 0.f, 0.f);
    #pragma unroll
    for (int k = 0; k < 8; k++) {
        int idx = (b * NCHUNK + wj * 8 + k) * HH + h;
        L += al[k] * g_l[idx];
        float4 a = ((const float4*)g_acc)[(((size_t)idx * DD) >> 2) + l];
        o.x += al[k] * a.x; o.y += al[k] * a.y;
        o.z += al[k] * a.z; o.w += al[k] * a.w;
    }
    osm[wj][l] = o;
    if (l == 0) Lsm[wj] = L;
    __syncthreads();

    if (wj == 0) {
        float4 t1 = osm[1][l], t2 = osm[2][l], t3 = osm[3][l];
        o.x += t1.x + t2.x + t3.x;
        o.y += t1.y + t2.y + t3.y;
        o.z += t1.z + t2.z + t3.z;
        o.w += t1.w + t2.w + t3.w;
        float inv = 1.0f / (Lsm[0] + Lsm[1] + Lsm[2] + Lsm[3]);
        o.x *= inv; o.y *= inv; o.z *= inv; o.w *= inv;
        ((float4*)out)[(size_t)bh * 32 + l] = o;
    }
}

extern "C" void kernel_launch(void* const* d_in, const int* in_sizes, int n_in,
                              void* d_out, int out_size) {
    const float* query   = (const float*)d_in[0];
    const float* k_cache = (const float*)d_in[1];
    const float* v_cache = (const float*)d_in[2];
    const int*   slots   = (const int*)d_in[3];
    const int*   pos     = (const int*)d_in[4];
    float*       out     = (float*)d_out;

    attn_partial<<<dim3(NCHUNK, BB), NT>>>(query, k_cache, v_cache, slots, pos);
    attn_combine<<<BB * HH, 128>>>(out);
}

// round 8
// speedup vs baseline: 1.2436x; 1.2436x over previous
#include <cuda_runtime.h>
#include <math.h>

#define BB      32
#define HH      32
#define KVHN    8
#define DD      128
#define SS      2048
#define NCHUNK  32
#define CS      64            // positions per chunk
#define HCS     32            // positions per table pass
#define NT      256           // 8 warps = 8 kv heads
#define SCALE   0.08838834764831845f
#define ROWF    (KVHN*DD)     // floats per slot row (1024)
#define FULLM   0xffffffffu

__device__ float g_acc[(size_t)BB * NCHUNK * HH * DD];  // 16 MB
__device__ float g_m[BB * NCHUNK * HH];
__device__ float g_l[BB * NCHUNK * HH];

__device__ __forceinline__ void l2_prefetch(const void* p) {
    asm volatile("prefetch.global.L2 [%0];" :: "l"(p));
}

// fp32 Cody-Waite reduction into [-pi,pi], then MUFU fast sin/cos.
// Reduced arg is in the accurate range for the fast path (~1e-7 abs err).
__device__ __forceinline__ void rope_sincos(float ang, float* s, float* c) {
    const float INV2PI = 0.15915494309189535f;
    const float C1 = 6.28125f;
    const float C2 = 0.0019353071795864769f;
    float n = rintf(ang * INV2PI);
    float r = fmaf(-n, C1, ang);
    r = fmaf(-n, C2, r);
    *s = __sinf(r);
    *c = __cosf(r);
}

__global__ __launch_bounds__(NT, 4) void attn_partial(
    const float* __restrict__ q,
    const float* __restrict__ kc,
    const float* __restrict__ vc,
    const int*   __restrict__ slot_map,
    const int*   __restrict__ pos)
{
    __shared__ float  cos_tab[HCS * 64];          // 8 KB (per pass)
    __shared__ float  sin_tab[HCS * 64];          // 8 KB
    __shared__ float4 q_sm[KVHN * 4 * 2 * 16];    // 16 KB  [head j][lo/hi][c]
    __shared__ float4 sc_sm[KVHN * CS];           // 8 KB   scores -> exp weights
    __shared__ int    slot_sm[CS];
    __shared__ float  pos_sm[CS];
    __shared__ float  invf_sm[64];

    const int b     = blockIdx.y;
    const int chunk = blockIdx.x;
    const int s0    = chunk * CS;
    const int tid   = threadIdx.x;
    const int w     = tid >> 5;            // warp = kv head
    const int l     = tid & 31;
    const int c     = l & 15;              // float4 chunk within row (K phase)
    const int r     = l >> 4;              // row parity within pair

    if (tid < 64) {
        float fi = (float)tid * 0.015625f;
        invf_sm[tid] = expf(-fi * 9.210340371976184f);
    }
    if (tid < CS) {
        slot_sm[tid] = slot_map[b * SS + s0 + tid];
        pos_sm[tid]  = (float)pos[b * SS + s0 + tid];
    }
    __syncthreads();

    // Warm L2 for the first K rows while the prologue runs.
    {
        int sw = tid >> 3;              // 32 positions warmed
        int lc = tid & 7;               // 8 lanes x 128B cover a 1KB.. (512B row x2 halves)
        int slot = slot_sm[sw];
        if (slot >= 0)
            l2_prefetch(kc + (size_t)slot * ROWF + (w & 3) * 2 * DD + lc * 32);
    }

    // Rope q (4 heads per warp) for dims {4c..4c+3, +64}; fold SCALE; store to shared.
    if (r == 0) {
        float pq = (float)pos[b * SS + SS - 1];
        float cq[4], sq[4];
        #pragma unroll
        for (int i = 0; i < 4; i++)
            rope_sincos(pq * invf_sm[4 * c + i], &sq[i], &cq[i]);
        #pragma unroll
        for (int j = 0; j < 4; j++) {
            const float4* qp = (const float4*)(q + ((size_t)(b * HH + w * 4 + j)) * DD);
            float4 alo = qp[c];
            float4 ahi = qp[c + 16];
            float4 ql, qh;
            ql.x = SCALE * (alo.x * cq[0] - ahi.x * sq[0]);
            qh.x = SCALE * (ahi.x * cq[0] + alo.x * sq[0]);
            ql.y = SCALE * (alo.y * cq[1] - ahi.y * sq[1]);
            qh.y = SCALE * (ahi.y * cq[1] + alo.y * sq[1]);
            ql.z = SCALE * (alo.z * cq[2] - ahi.z * sq[2]);
            qh.z = SCALE * (ahi.z * cq[2] + alo.z * sq[2]);
            ql.w = SCALE * (alo.w * cq[3] - ahi.w * sq[3]);
            qh.w = SCALE * (ahi.w * cq[3] + alo.w * sq[3]);
            q_sm[((w * 4 + j) * 2 + 0) * 16 + c] = ql;
            q_sm[((w * 4 + j) * 2 + 1) * 16 + c] = qh;
        }
    }

    // ---- K phase in two passes of HCS positions (table rebuilt between) ----
    float m0 = -1e30f, m1 = -1e30f, m2 = -1e30f, m3 = -1e30f;

    #pragma unroll
    for (int pass = 0; pass < 2; pass++) {
        // build cos/sin for positions [pass*HCS, pass*HCS+HCS)
        for (int idx = tid; idx < HCS * 64; idx += NT) {
            int s = idx >> 6;
            int i = idx & 63;
            float sv, cv;
            rope_sincos(pos_sm[pass * HCS + s] * invf_sm[i], &sv, &cv);
            cos_tab[idx] = cv;
            sin_tab[idx] = sv;
        }
        __syncthreads();

        #pragma unroll 4
        for (int sp = 0; sp < HCS; sp += 2) {
            const int sl = sp + r;                 // table-local position
            const int s  = pass * HCS + sl;        // chunk-local position
            const int slot = slot_sm[s];

            // prefetch K row 8 positions ahead into L2 (no reg cost)
            {
                int sf = s + 8;
                if (sf < CS) {
                    int slotf = slot_sm[sf];
                    if (slotf >= 0) {
                        const float* pp = kc + (size_t)slotf * ROWF + w * DD + 4 * c;
                        l2_prefetch(pp);
                        l2_prefetch(pp + 64);
                    }
                }
            }

            float4 klo = make_float4(0.f, 0.f, 0.f, 0.f);
            float4 khi = make_float4(0.f, 0.f, 0.f, 0.f);
            if (slot >= 0) {
                const float* kp = kc + (size_t)slot * ROWF + w * DD + 4 * c;
                klo = *(const float4*)kp;
                khi = *(const float4*)(kp + 64);
            }
            const float4 co = *(const float4*)&cos_tab[sl * 64 + 4 * c];
            const float4 si = *(const float4*)&sin_tab[sl * 64 + 4 * c];

            float rlx = klo.x * co.x - khi.x * si.x, rhx = khi.x * co.x + klo.x * si.x;
            float rly = klo.y * co.y - khi.y * si.y, rhy = khi.y * co.y + klo.y * si.y;
            float rlz = klo.z * co.z - khi.z * si.z, rhz = khi.z * co.z + klo.z * si.z;
            float rlw = klo.w * co.w - khi.w * si.w, rhw = khi.w * co.w + klo.w * si.w;

            float p[4];
            #pragma unroll
            for (int j = 0; j < 4; j++) {
                float4 ql = q_sm[((w * 4 + j) * 2 + 0) * 16 + c];
                float4 qh = q_sm[((w * 4 + j) * 2 + 1) * 16 + c];
                p[j] = ql.x * rlx + ql.y * rly + ql.z * rlz + ql.w * rlw
                     + qh.x * rhx + qh.y * rhy + qh.z * rhz + qh.w * rhw;
            }
            #pragma unroll
            for (int off = 1; off <= 8; off <<= 1) {
                p[0] += __shfl_xor_sync(FULLM, p[0], off);
                p[1] += __shfl_xor_sync(FULLM, p[1], off);
                p[2] += __shfl_xor_sync(FULLM, p[2], off);
                p[3] += __shfl_xor_sync(FULLM, p[3], off);
            }
            m0 = fmaxf(m0, p[0]); m1 = fmaxf(m1, p[1]);
            m2 = fmaxf(m2, p[2]); m3 = fmaxf(m3, p[3]);
            if (c == 0) sc_sm[w * CS + s] = make_float4(p[0], p[1], p[2], p[3]);
        }
        __syncthreads();   // protect table before rebuild / reuse
    }

    // merge the two half-warp maxima
    m0 = fmaxf(m0, __shfl_xor_sync(FULLM, m0, 16));
    m1 = fmaxf(m1, __shfl_xor_sync(FULLM, m1, 16));
    m2 = fmaxf(m2, __shfl_xor_sync(FULLM, m2, 16));
    m3 = fmaxf(m3, __shfl_xor_sync(FULLM, m3, 16));

    // ---- scores -> exp weights in shared (4 MUFU per lane total) ----
    {
        float4 sca = sc_sm[w * CS + l];
        sca.x = __expf(sca.x - m0); sca.y = __expf(sca.y - m1);
        sca.z = __expf(sca.z - m2); sca.w = __expf(sca.w - m3);
        sc_sm[w * CS + l] = sca;
        float4 scb = sc_sm[w * CS + 32 + l];
        scb.x = __expf(scb.x - m0); scb.y = __expf(scb.y - m1);
        scb.z = __expf(scb.z - m2); scb.w = __expf(scb.w - m3);
        sc_sm[w * CS + 32 + l] = scb;
    }
    __syncwarp();

    // ---- V phase: lane owns dims 4l..4l+3, one row per iteration ----
    float4 a0 = make_float4(0,0,0,0), a1 = a0, a2 = a0, a3 = a0;
    float l0 = 0.f, l1 = 0.f, l2 = 0.f, l3 = 0.f;
    #pragma unroll 4
    for (int s = 0; s < CS; s++) {
        // prefetch V row 4 ahead
        {
            int sf = s + 4;
            if (sf < CS) {
                int slotf = slot_sm[sf];
                if (slotf >= 0)
                    l2_prefetch(vc + (size_t)slotf * ROWF + w * DD + 4 * l);
            }
        }
        const float4 e = sc_sm[w * CS + s];     // broadcast
        l0 += e.x; l1 += e.y; l2 += e.z; l3 += e.w;
        const int slot = slot_sm[s];
        float4 v4 = make_float4(0.f, 0.f, 0.f, 0.f);
        if (slot >= 0)
            v4 = *(const float4*)(vc + (size_t)slot * ROWF + w * DD + 4 * l);
        a0.x += e.x * v4.x; a0.y += e.x * v4.y; a0.z += e.x * v4.z; a0.w += e.x * v4.w;
        a1.x += e.y * v4.x; a1.y += e.y * v4.y; a1.z += e.y * v4.z; a1.w += e.y * v4.w;
        a2.x += e.z * v4.x; a2.y += e.z * v4.y; a2.z += e.z * v4.z; a2.w += e.z * v4.w;
        a3.x += e.w * v4.x; a3.y += e.w * v4.y; a3.z += e.w * v4.z; a3.w += e.w * v4.w;
    }

    // ---- Write partials (float4, coalesced) ----
    {
        size_t base = (((size_t)b * NCHUNK + chunk) * HH + w * 4) * DD;
        float4* ga = (float4*)g_acc;
        ga[(base >> 2) + l]            = a0;
        ga[((base + DD) >> 2) + l]     = a1;
        ga[((base + 2 * DD) >> 2) + l] = a2;
        ga[((base + 3 * DD) >> 2) + l] = a3;
    }
    if (l == 0) {
        int mb = (b * NCHUNK + chunk) * HH + w * 4;
        g_m[mb + 0] = m0; g_m[mb + 1] = m1; g_m[mb + 2] = m2; g_m[mb + 3] = m3;
        g_l[mb + 0] = l0; g_l[mb + 1] = l1; g_l[mb + 2] = l2; g_l[mb + 3] = l3;
    }
}

// Combine: one block per (b,h); 4 warps x 8 chunks each; merge via shared.
__global__ __launch_bounds__(128) void attn_combine(float* __restrict__ out)
{
    __shared__ float4 osm[4][32];
    __shared__ float  Lsm[4];

    const int bh = blockIdx.x;
    const int b  = bh >> 5;
    const int h  = bh & 31;
    const int wj = threadIdx.x >> 5;
    const int l  = threadIdx.x & 31;

    float mraw = g_m[(b * NCHUNK + l) * HH + h];
    float M = mraw;
    #pragma unroll
    for (int off = 16; off > 0; off >>= 1)
        M = fmaxf(M, __shfl_xor_sync(FULLM, M, off));

    // precompute all 8 alpha factors so the load loop has full MLP
    float al[8];
    #pragma unroll
    for (int k = 0; k < 8; k++)
        al[k] = __expf(__shfl_sync(FULLM, mraw, wj * 8 + k) - M);

    float L = 0.f;
    float4 o = make_float4(0.f, 0.f, 0.f, 0.f);
    #pragma unroll
    for (int k = 0; k < 8; k++) {
        int idx = (b * NCHUNK + wj * 8 + k) * HH + h;
        L += al[k] * g_l[idx];
        float4 a = ((const float4*)g_acc)[(((size_t)idx * DD) >> 2) + l];
        o.x += al[k] * a.x; o.y += al[k] * a.y;
        o.z += al[k] * a.z; o.w += al[k] * a.w;
    }
    osm[wj][l] = o;
    if (l == 0) Lsm[wj] = L;
    __syncthreads();

    if (wj == 0) {
        float4 t1 = osm[1][l], t2 = osm[2][l], t3 = osm[3][l];
        o.x += t1.x + t2.x + t3.x;
        o.y += t1.y + t2.y + t3.y;
        o.z += t1.z + t2.z + t3.z;
        o.w += t1.w + t2.w + t3.w;
        float inv = 1.0f / (Lsm[0] + Lsm[1] + Lsm[2] + Lsm[3]);
        o.x *= inv; o.y *= inv; o.z *= inv; o.w *= inv;
        ((float4*)out)[(size_t)bh * 32 + l] = o;
    }
}

extern "C" void kernel_launch(void* const* d_in, const int* in_sizes, int n_in,
                              void* d_out, int out_size) {
    const float* query   = (const float*)d_in[0];
    const float* k_cache = (const float*)d_in[1];
    const float* v_cache = (const float*)d_in[2];
    const int*   slots   = (const int*)d_in[3];
    const int*   pos     = (const int*)d_in[4];
    float*       out     = (float*)d_out;

    attn_partial<<<dim3(NCHUNK, BB), NT>>>(query, k_cache, v_cache, slots, pos);
    attn_combine<<<BB * HH, 128>>>(out);
}